// round 4
// baseline (speedup 1.0000x reference)
#include <cuda_runtime.h>

// TemporalGCN fused persistent kernel, round 2.
// Pipeline per (b,t) tile (using associativity (A@x)@W^T == A@(x@W^T)):
//   H0 = x @ W0^T        [24(pad) x 128], K=192
//   g1 = relu(A @ H0 + b0)
//   H1 = g1 @ W1^T       K=128
//   g2 = relu(A @ H1 + b1);  out = mean_c g2
//
// Weights k-major in SMEM (conflict-free LDS.128 on h), broadcast operands
// (x, g1, A) stored duplicated {v,v} so fma.rn.f32x2 needs no pack MOVs.

#define CC 22
#define CP 24          // padded C
#define FF 192
#define HH 128
#define NTILES (32 * 512)

#define THREADS 384    // 32 h-groups (4 h each) x 12 c-groups (2 c each)
#define GRID 148

// SMEM float offsets
#define OFF_W0 0                         // [192][128] k-major       24576
#define OFF_W1 (OFF_W0 + FF * HH)        // [128][128] k-major       16384
#define OFF_R1 (OFF_W1 + HH * HH)        // xsd[24][384] / g1d[24][256] / red[12][128]
#define R1_SZ  (CP * 2 * FF)             // 9216
#define OFF_AS (OFF_R1 + R1_SZ)          // Asd[24][48] duplicated   1152
#define OFF_H  (OFF_AS + CP * 48)        // H0/H1 [24][128]          3072
#define OFF_B0 (OFF_H + CP * HH)
#define OFF_B1 (OFF_B0 + HH)
#define SMEM_FLOATS (OFF_B1 + HH)        // 54656
#define SMEM_BYTES (SMEM_FLOATS * 4)     // 218624

__device__ __forceinline__ float2 ffma2(float2 a, float2 b, float2 c) {
    float2 d;
    asm("fma.rn.f32x2 %0, %1, %2, %3;"
        : "=l"(*reinterpret_cast<unsigned long long*>(&d))
        : "l"(*reinterpret_cast<const unsigned long long*>(&a)),
          "l"(*reinterpret_cast<const unsigned long long*>(&b)),
          "l"(*reinterpret_cast<const unsigned long long*>(&c)));
    return d;
}

// One register-blocked GEMM: out[c0..c0+1][hb..hb+3] = xd @ Wk
// xd: duplicated rows, pitch 2*K.  Wk: k-major [K][128].
template<int K>
__device__ __forceinline__ void gemm_2x4(const float* __restrict__ Wk,
                                         const float* __restrict__ xr0,
                                         const float* __restrict__ xr1,
                                         int hb, float* __restrict__ Hs,
                                         int c0)
{
    float2 a00 = make_float2(0.f, 0.f), a01 = a00, a10 = a00, a11 = a00;
    #pragma unroll 8
    for (int kb = 0; kb < K / 4; kb++) {
        const float* wk = Wk + (kb * 4) * HH + hb;
        float4 w[4];
        #pragma unroll
        for (int kk = 0; kk < 4; kk++)
            w[kk] = *reinterpret_cast<const float4*>(wk + kk * HH);
        #pragma unroll
        for (int kk = 0; kk < 4; kk++) {
            float2 wlo = make_float2(w[kk].x, w[kk].y);
            float2 whi = make_float2(w[kk].z, w[kk].w);
            float2 xa = *reinterpret_cast<const float2*>(xr0 + 2 * (kb * 4 + kk));
            float2 xb = *reinterpret_cast<const float2*>(xr1 + 2 * (kb * 4 + kk));
            a00 = ffma2(xa, wlo, a00);
            a01 = ffma2(xa, whi, a01);
            a10 = ffma2(xb, wlo, a10);
            a11 = ffma2(xb, whi, a11);
        }
    }
    *reinterpret_cast<float4*>(Hs + c0 * HH + hb) =
        make_float4(a00.x, a00.y, a01.x, a01.y);
    *reinterpret_cast<float4*>(Hs + (c0 + 1) * HH + hb) =
        make_float4(a10.x, a10.y, a11.x, a11.y);
}

extern "C" __global__ void __launch_bounds__(THREADS, 1)
tgcn_kernel(const float* __restrict__ x, const float* __restrict__ A,
            const float* __restrict__ W0, const float* __restrict__ b0,
            const float* __restrict__ W1, const float* __restrict__ b1,
            float* __restrict__ out)
{
    extern __shared__ float smem[];
    float* Ws0 = smem + OFF_W0;
    float* Ws1 = smem + OFF_W1;
    float* R1  = smem + OFF_R1;   // xsd pitch 384 / g1d pitch 256 / red pitch 128
    float* Asd = smem + OFF_AS;   // pitch 48, duplicated
    float* Hs  = smem + OFF_H;    // pitch 128
    float* b0s = smem + OFF_B0;
    float* b1s = smem + OFF_B1;

    const int tid = threadIdx.x;

    // ---- one-time init: transpose weights to k-major, biases, Asd pad rows ----
    for (int i = tid; i < HH * FF; i += THREADS) {
        int h = i / FF, k = i - h * FF;
        Ws0[k * HH + h] = W0[i];
    }
    for (int i = tid; i < HH * HH; i += THREADS) {
        int h = i >> 7, k = i & 127;
        Ws1[k * HH + h] = W1[i];
    }
    if (tid < HH) { b0s[tid] = b0[tid]; b1s[tid] = b1[tid]; }
    for (int i = tid; i < 2 * 48; i += THREADS) Asd[CC * 48 + i] = 0.f;  // pad rows 22,23
    __syncthreads();

    const int hg = tid & 31;
    const int cg = tid >> 5;          // == warp id; warp-uniform
    const int hb = hg * 4;
    const int c0 = cg * 2;

    for (int tile = blockIdx.x; tile < NTILES; tile += gridDim.x) {
        // ---- load x (duplicated) and A (duplicated) ----
        {
            const float4* xg = reinterpret_cast<const float4*>(x + (size_t)tile * (CC * FF));
            #pragma unroll
            for (int it = 0; it < 3; it++) {
                int i = tid + it * THREADS;
                if (i < CC * FF / 4) {
                    float4 v = xg[i];
                    int c = i / 48;
                    int k = 4 * (i - c * 48);
                    float* dst = R1 + c * (2 * FF) + 2 * k;
                    *reinterpret_cast<float4*>(dst)     = make_float4(v.x, v.x, v.y, v.y);
                    *reinterpret_cast<float4*>(dst + 4) = make_float4(v.z, v.z, v.w, v.w);
                }
            }
            const float* Ag = A + (size_t)tile * (CC * CC);
            #pragma unroll
            for (int it = 0; it < 2; it++) {
                int i = tid + it * THREADS;
                if (i < CC * CC) {
                    float a = Ag[i];
                    int c = i / 22, j = i - 22 * c;
                    *reinterpret_cast<float2*>(Asd + c * 48 + 2 * j) = make_float2(a, a);
                }
            }
        }
        __syncthreads();

        // ---- GEMM1: H0 = xd @ Ws0  (K=192) ----
        gemm_2x4<FF>(Ws0, R1 + c0 * (2 * FF), R1 + (c0 + 1) * (2 * FF), hb, Hs, c0);
        __syncthreads();

        // ---- mix1: g1 = relu(A @ H0 + b0), store duplicated into R1 (pitch 256) ----
        {
            float2 m00 = make_float2(0.f, 0.f), m01 = m00, m10 = m00, m11 = m00;
            #pragma unroll
            for (int j = 0; j < CC; j++) {
                float4 hv = *reinterpret_cast<const float4*>(Hs + j * HH + hb);
                float2 A0 = *reinterpret_cast<const float2*>(Asd + c0 * 48 + 2 * j);
                float2 A1 = *reinterpret_cast<const float2*>(Asd + (c0 + 1) * 48 + 2 * j);
                float2 hlo = make_float2(hv.x, hv.y);
                float2 hhi = make_float2(hv.z, hv.w);
                m00 = ffma2(A0, hlo, m00);
                m01 = ffma2(A0, hhi, m01);
                m10 = ffma2(A1, hlo, m10);
                m11 = ffma2(A1, hhi, m11);
            }
            float4 bb = *reinterpret_cast<const float4*>(b0s + hb);
            float v0 = fmaxf(m00.x + bb.x, 0.f), v1 = fmaxf(m00.y + bb.y, 0.f);
            float v2 = fmaxf(m01.x + bb.z, 0.f), v3 = fmaxf(m01.y + bb.w, 0.f);
            float u0 = fmaxf(m10.x + bb.x, 0.f), u1 = fmaxf(m10.y + bb.y, 0.f);
            float u2 = fmaxf(m11.x + bb.z, 0.f), u3 = fmaxf(m11.y + bb.w, 0.f);
            float* g0 = R1 + c0 * (2 * HH) + 2 * hb;
            float* g1r = R1 + (c0 + 1) * (2 * HH) + 2 * hb;
            *reinterpret_cast<float4*>(g0)      = make_float4(v0, v0, v1, v1);
            *reinterpret_cast<float4*>(g0 + 4)  = make_float4(v2, v2, v3, v3);
            *reinterpret_cast<float4*>(g1r)     = make_float4(u0, u0, u1, u1);
            *reinterpret_cast<float4*>(g1r + 4) = make_float4(u2, u2, u3, u3);
        }
        __syncthreads();

        // ---- GEMM2: H1 = g1d @ Ws1  (K=128), H1 aliases H0 ----
        gemm_2x4<HH>(Ws1, R1 + c0 * (2 * HH), R1 + (c0 + 1) * (2 * HH), hb, Hs, c0);
        __syncthreads();

        // ---- mix2 + relu + partial mean: red[cg][h] = sum over this thread's c ----
        {
            float2 m00 = make_float2(0.f, 0.f), m01 = m00, m10 = m00, m11 = m00;
            #pragma unroll
            for (int j = 0; j < CC; j++) {
                float4 hv = *reinterpret_cast<const float4*>(Hs + j * HH + hb);
                float2 A0 = *reinterpret_cast<const float2*>(Asd + c0 * 48 + 2 * j);
                float2 A1 = *reinterpret_cast<const float2*>(Asd + (c0 + 1) * 48 + 2 * j);
                float2 hlo = make_float2(hv.x, hv.y);
                float2 hhi = make_float2(hv.z, hv.w);
                m00 = ffma2(A0, hlo, m00);
                m01 = ffma2(A0, hhi, m01);
                m10 = ffma2(A1, hlo, m10);
                m11 = ffma2(A1, hhi, m11);
            }
            float4 bb = *reinterpret_cast<const float4*>(b1s + hb);
            float4 s;
            if (cg < 11) {
                s.x = fmaxf(m00.x + bb.x, 0.f) + fmaxf(m10.x + bb.x, 0.f);
                s.y = fmaxf(m00.y + bb.y, 0.f) + fmaxf(m10.y + bb.y, 0.f);
                s.z = fmaxf(m01.x + bb.z, 0.f) + fmaxf(m11.x + bb.z, 0.f);
                s.w = fmaxf(m01.y + bb.w, 0.f) + fmaxf(m11.y + bb.w, 0.f);
            } else {
                s = make_float4(0.f, 0.f, 0.f, 0.f);
            }
            *reinterpret_cast<float4*>(R1 + cg * HH + hb) = s;   // red region
        }
        __syncthreads();

        // ---- final reduce over 11 c-group partials -> out ----
        if (tid < HH) {
            float s = 0.f;
            #pragma unroll
            for (int g = 0; g < 11; g++) s += R1[g * HH + tid];
            out[(size_t)tile * HH + tid] = s * (1.f / (float)CC);
        }
        __syncthreads();   // protect R1/Asd before next tile's load
    }
}

extern "C" void kernel_launch(void* const* d_in, const int* in_sizes, int n_in,
                              void* d_out, int out_size)
{
    const float* x  = (const float*)d_in[0];
    const float* A  = (const float*)d_in[1];
    const float* W0 = (const float*)d_in[2];
    const float* b0 = (const float*)d_in[3];
    const float* W1 = (const float*)d_in[4];
    const float* b1 = (const float*)d_in[5];
    float* out = (float*)d_out;

    cudaFuncSetAttribute(tgcn_kernel, cudaFuncAttributeMaxDynamicSharedMemorySize, SMEM_BYTES);
    tgcn_kernel<<<GRID, THREADS, SMEM_BYTES>>>(x, A, W0, b0, W1, b1, out);
}